// round 4
// baseline (speedup 1.0000x reference)
#include <cuda_runtime.h>

// Inputs (metadata order):
//   0: x        float32 [N=262144]
//   1: Param_W  float32 [1280]
//   2: Param_b  float32 [16]
//   3: w_rows   int32   [E=16777216]
//   4: w_cols   int32   [E]
//   5: w_params int32   [E]
//   6: b_params int32   [N]
// Output: float32 [N]

__global__ void bias_init_kernel(const float* __restrict__ Pb,
                                 const int* __restrict__ b_params,
                                 float* __restrict__ out, int n) {
    int i = blockIdx.x * blockDim.x + threadIdx.x;
    if (i < n) {
        out[i] = __ldg(&Pb[b_params[i]]);
    }
}

// 4 edges per thread via int4 loads of the three index streams.
// atomicAdd with discarded return -> REDG (no-return reduction) on sm_103a.
__global__ void __launch_bounds__(256) edge_scatter_kernel(
    const float* __restrict__ x,
    const float* __restrict__ Pw,
    const int4* __restrict__ rows4,
    const int4* __restrict__ cols4,
    const int4* __restrict__ params4,
    float* __restrict__ out,
    int e4) {
    int i = blockIdx.x * blockDim.x + threadIdx.x;
    if (i >= e4) return;

    int4 r = rows4[i];
    int4 c = cols4[i];
    int4 p = params4[i];

    // Fire all gathers first for maximum MLP (x gathers are L2-hit, Pw is L1-hit).
    float w0 = __ldg(&Pw[p.x]);
    float w1 = __ldg(&Pw[p.y]);
    float w2 = __ldg(&Pw[p.z]);
    float w3 = __ldg(&Pw[p.w]);
    float x0 = __ldg(&x[c.x]);
    float x1 = __ldg(&x[c.y]);
    float x2 = __ldg(&x[c.z]);
    float x3 = __ldg(&x[c.w]);

    atomicAdd(&out[r.x], w0 * x0);
    atomicAdd(&out[r.y], w1 * x1);
    atomicAdd(&out[r.z], w2 * x2);
    atomicAdd(&out[r.w], w3 * x3);
}

extern "C" void kernel_launch(void* const* d_in, const int* in_sizes, int n_in,
                              void* d_out, int out_size) {
    const float* x        = (const float*)d_in[0];
    const float* Pw       = (const float*)d_in[1];
    const float* Pb       = (const float*)d_in[2];
    const int*   w_rows   = (const int*)d_in[3];
    const int*   w_cols   = (const int*)d_in[4];
    const int*   w_params = (const int*)d_in[5];
    const int*   b_params = (const int*)d_in[6];
    float* out = (float*)d_out;

    int N = out_size;            // 262144
    int E = in_sizes[3];         // 16777216

    // 1) out[i] = Param_b[b_params[i]]
    {
        int threads = 256;
        int blocks = (N + threads - 1) / threads;
        bias_init_kernel<<<blocks, threads>>>(Pb, b_params, out, N);
    }

    // 2) scatter-add edges (stream-ordered after bias init)
    {
        int e4 = E / 4;          // E divisible by 4
        int threads = 256;
        int blocks = (e4 + threads - 1) / threads;
        edge_scatter_kernel<<<blocks, threads>>>(
            x, Pw,
            (const int4*)w_rows, (const int4*)w_cols, (const int4*)w_params,
            out, e4);
    }
}